// round 9
// baseline (speedup 1.0000x reference)
#include <cuda_runtime.h>
#include <cuda_bf16.h>
#include <math.h>

// ---------------------------------------------------------------------------
// Problem constants
// ---------------------------------------------------------------------------
#define N_NODES   10000
#define N_EDGES   250000
#define F_CH      32
#define HIDDEN    64
#define NPATH     11
#define RCOLS     (NPATH * F_CH)   // 352
#define FEAT      288              // 9*F

// Path tables (i, j, k) — compile-time foldable device constexpr accessors.
__device__ constexpr int PI_(int p) { constexpr int v[NPATH] = {0,0,0,1,1,1,1,2,2,2,2}; return v[p]; }
__device__ constexpr int PJ_(int p) { constexpr int v[NPATH] = {0,1,2,0,1,1,2,0,1,2,2}; return v[p]; }
__device__ constexpr int PK_(int p) { constexpr int v[NPATH] = {0,1,2,1,0,2,1,2,1,0,2}; return v[p]; }
// M-table offsets: sizes (2i+1)(2k+1) = 1,3,5,9,3,15,9,25,15,5,25  (total 115)
__device__ constexpr int MOFF_(int p){ constexpr int v[NPATH+1] = {0,1,4,9,18,21,36,45,70,85,90,115}; return v[p]; }
#define MTOT 115

// ---------------------------------------------------------------------------
// Device scratch (static allocation — no runtime alloc APIs)
// ---------------------------------------------------------------------------
__device__ float g_radial[(long)N_EDGES * RCOLS];   // 352 MB
__device__ float g_sph[(long)N_EDGES * 8];          // 8 MB  (y1[3], y2[5]; y0==1 implicit)
__device__ float g_W3J[NPATH * 125];                // padded [p][a(5)][b(5)][c(5)], PATH_W*0.2 folded in

// ---------------------------------------------------------------------------
// Kernel A: compute Wigner-3j tensors on device, mirroring the reference
// (_su2_cg -> _q -> _w3j, Re/Im norm selection, Frobenius normalization).
// Runs every launch; 11 blocks x 128 threads, double precision, ~µs.
// ---------------------------------------------------------------------------
__device__ __forceinline__ double d_fact(int n) {
    const double f[9] = {1.0, 1.0, 2.0, 6.0, 24.0, 120.0, 720.0, 5040.0, 40320.0};
    return f[n];
}

__device__ double su2_cg(int j1, int j2, int j3, int m1, int m2, int m3) {
    if (m1 + m2 != m3) return 0.0;
    double pref = sqrt((2.0*j3 + 1.0) * d_fact(j1+j2-j3) * d_fact(j1-j2+j3) *
                       d_fact(-j1+j2+j3) / d_fact(j1+j2+j3+1));
    pref *= sqrt(d_fact(j3+m3) * d_fact(j3-m3) * d_fact(j1-m1) *
                 d_fact(j1+m1) * d_fact(j2-m2) * d_fact(j2+m2));
    double s = 0.0;
    for (int k = 0; k <= j1 + j2 - j3; ++k) {
        int d0 = k, d1 = j1+j2-j3-k, d2 = j1-m1-k, d3 = j2+m2-k,
            d4 = j3-j2+m1+k, d5 = j3-j1-m2+k;
        if (d0 < 0 || d1 < 0 || d2 < 0 || d3 < 0 || d4 < 0 || d5 < 0) continue;
        double term = 1.0 / (d_fact(d0)*d_fact(d1)*d_fact(d2)*d_fact(d3)*d_fact(d4)*d_fact(d5));
        s += (k & 1) ? -term : term;
    }
    return pref * s;
}

// q(l)[row][col] including the (-i)^l prefactor.
__device__ void q_entry(int l, int row, int col, double& qr, double& qi) {
    const double is2 = 0.70710678118654752440;
    int m = row - l;
    double a = 0.0, b = 0.0;
    if (m < 0) {
        if (col == l - m) a = is2;        // l + |m|
        if (col == l + m) b = -is2;       // l - |m|
    } else if (m == 0) {
        if (col == l) a = 1.0;
    } else {
        double sgn = (m & 1) ? -1.0 : 1.0;
        if (col == l + m) a = sgn * is2;
        if (col == l - m) b = sgn * is2;
    }
    if (l == 1) { double na = b, nb = -a; a = na; b = nb; }   // * (-i)
    else if (l == 2) { a = -a; b = -b; }                       // * (-i)^2
    qr = a; qi = b;
}

__global__ void w3j_init_kernel() {
    int p = blockIdx.x;
    int l1 = PI_(p), l2 = PJ_(p), l3 = PK_(p);
    int n1 = 2*l1 + 1, n2 = 2*l2 + 1, n3 = 2*l3 + 1;
    int tot = n1 * n2 * n3;
    int tid = threadIdx.x;

    __shared__ double sC[125];
    __shared__ double sWr[125], sWi[125];
    __shared__ double snr, sni;

    for (int idx = tid; idx < 125; idx += blockDim.x) g_W3J[p*125 + idx] = 0.0f;

    for (int idx = tid; idx < tot; idx += blockDim.x) {
        int a = idx / (n2*n3), r = idx % (n2*n3), b = r / n3, c = r % n3;
        sC[(a*n2 + b)*n3 + c] = su2_cg(l1, l2, l3, a - l1, b - l2, c - l3);
    }
    if (tid == 0) { snr = 0.0; sni = 0.0; }
    __syncthreads();

    for (int idx = tid; idx < tot; idx += blockDim.x) {
        int j  = idx / (n2*n3), r = idx % (n2*n3);
        int lq = r / n3, nn = r % n3;
        double wr = 0.0, wi = 0.0;
        for (int a = 0; a < n1; ++a) {
            double q1r, q1i; q_entry(l1, a, j, q1r, q1i);
            for (int b = 0; b < n2; ++b) {
                double q2r, q2i; q_entry(l2, b, lq, q2r, q2i);
                double tr = q1r*q2r - q1i*q2i;
                double ti = q1r*q2i + q1i*q2r;
                for (int c = 0; c < n3; ++c) {
                    double q3r, q3i; q_entry(l3, c, nn, q3r, q3i);
                    double ur = tr*q3r + ti*q3i;     // * conj(q3)
                    double ui = ti*q3r - tr*q3i;
                    double cg = sC[(a*n2 + b)*n3 + c];
                    wr += ur * cg; wi += ui * cg;
                }
            }
        }
        sWr[idx] = wr; sWi[idx] = wi;
        atomicAdd(&snr, wr*wr);
        atomicAdd(&sni, wi*wi);
    }
    __syncthreads();

    bool useR = (snr >= sni);
    double norm = sqrt(useR ? snr : sni);
    // PATH_W[p] = sqrt((2k+1)/cnt[k]), cnt = {3,4,4}; fold 1/sqrt(AVG_NEIGHBORS)=0.2
    const double cnt = (l3 == 0) ? 3.0 : 4.0;
    double scale = sqrt((2.0*l3 + 1.0) / cnt) * 0.2 / norm;

    for (int idx = tid; idx < tot; idx += blockDim.x) {
        int j  = idx / (n2*n3), r = idx % (n2*n3);
        int lq = r / n3, nn = r % n3;
        double v = (useR ? sWr[idx] : sWi[idx]) * scale;
        g_W3J[p*125 + (j*5 + lq)*5 + nn] = (float)v;
    }
}

// ---------------------------------------------------------------------------
// Kernel B: per-edge geometry + bessel + MLP(8->64->352) + cutoff.
// 64 edges/block, 256 threads. Phase B: register-tiled GEMM, 88 FMA per
// 19 conflict-free LDS per k-step. Static smem = 44 KB.
// ---------------------------------------------------------------------------
__global__ __launch_bounds__(256)
void radial_kernel(const float* __restrict__ pos,
                   const int*   __restrict__ src,
                   const int*   __restrict__ dst,
                   const float* __restrict__ w1,
                   const float* __restrict__ b1,
                   const float* __restrict__ w2,
                   const float* __restrict__ b2)
{
    __shared__ float s_w1[8*64];
    __shared__ float s_b1[64];
    __shared__ float s_bes[64][9];        // pad 9: conflict-free stride
    __shared__ float s_cut[64];
    __shared__ float s_h[64][65];         // pad 65
    __shared__ float s_w2[16][352];       // K-chunk of w2

    const int tid = threadIdx.x;
    const long ebase = (long)blockIdx.x * 64;

    for (int i = tid; i < 512; i += 256) s_w1[i] = w1[i];
    if (tid < 64) s_b1[tid] = b1[tid];

    if (tid < 64) {
        long e = ebase + tid;
        float bes[8];
        if (e < N_EDGES) {
            int sn = src[e], dn = dst[e];
            float px = pos[3*sn]   - pos[3*dn];
            float py = pos[3*sn+1] - pos[3*dn+1];
            float pz = pos[3*sn+2] - pos[3*dn+2];
            float d = sqrtf(px*px + py*py + pz*pz);
            float invd = 1.0f / fmaxf(d, 1e-12f);
            float x = px*invd, y = py*invd, z = pz*invd;
            const float s3   = 1.7320508075688772f;
            const float s15  = 3.8729833462074170f;
            const float s5h  = 1.1180339887498949f;   // sqrt(5)/2
            const float s15h = 1.9364916731037085f;   // sqrt(15)/2
            float sph[8];
            sph[0] = s3*y;  sph[1] = s3*z;  sph[2] = s3*x;
            sph[3] = s15*x*y; sph[4] = s15*y*z; sph[5] = s5h*(3.0f*z*z - 1.0f);
            sph[6] = s15*x*z; sph[7] = s15h*(x*x - y*y);
            #pragma unroll
            for (int q = 0; q < 8; ++q) g_sph[e*8 + q] = sph[q];

            float t  = d * 0.2f;                         // d / BESSEL_END
            float mask = (t > 0.0f && t < 1.0f) ? 1.0f : 0.0f;
            float invt = (t > 0.0f) ? (1.0f / t) : 1.0f;
            const float cb = 0.63245553203367587f;       // sqrt(2/5)
            const float pif = 3.14159265358979323846f;
            #pragma unroll
            for (int n = 0; n < 8; ++n)
                bes[n] = cb * sinf((float)(n+1) * pif * t) * invt * mask;

            float u = d * 0.25f;                         // d / RCUT
            float u2 = u*u, u4 = u2*u2, u5 = u4*u;
            s_cut[tid] = (1.0f - 6.0f*u5 + 5.0f*u5*u) * ((d < 4.0f) ? 1.0f : 0.0f);
        } else {
            #pragma unroll
            for (int n = 0; n < 8; ++n) bes[n] = 0.0f;
            s_cut[tid] = 0.0f;
        }
        #pragma unroll
        for (int n = 0; n < 8; ++n) s_bes[tid][n] = bes[n];
    }
    __syncthreads();

    // Phase A: h = silu(bessel @ w1 + b1); thread -> (e = tid&63, 16 k's)
    {
        const int e = tid & 63, kg = tid >> 6;
        #pragma unroll
        for (int i2 = 0; i2 < 16; ++i2) {
            int k = kg*16 + i2;
            float acc = s_b1[k];
            #pragma unroll
            for (int n = 0; n < 8; ++n) acc += s_bes[e][n] * s_w1[n*64 + k];
            float sig = 1.0f / (1.0f + expf(-acc));
            s_h[e][k] = acc * sig;
        }
    }

    // Phase B: radial = h @ w2; thread (g = tid>>5 : 8 edges, c0 = tid&31 : 11 cols)
    const int c0 = tid & 31, g = tid >> 5;
    float acc[8][11];
    #pragma unroll
    for (int a = 0; a < 8; ++a)
        #pragma unroll
        for (int j = 0; j < 11; ++j) acc[a][j] = 0.0f;

    for (int k0 = 0; k0 < 64; k0 += 16) {
        __syncthreads();
        const float4* srcv = reinterpret_cast<const float4*>(w2 + k0*352);
        float4* dstv = reinterpret_cast<float4*>(&s_w2[0][0]);
        for (int idx = tid; idx < 16*352/4; idx += 256) dstv[idx] = srcv[idx];
        __syncthreads();

        #pragma unroll
        for (int kk = 0; kk < 16; ++kk) {
            float hreg[8];
            #pragma unroll
            for (int a = 0; a < 8; ++a) hreg[a] = s_h[g*8 + a][k0 + kk];
            float wreg[11];
            #pragma unroll
            for (int j = 0; j < 11; ++j) wreg[j] = s_w2[kk][c0 + 32*j];
            #pragma unroll
            for (int a = 0; a < 8; ++a)
                #pragma unroll
                for (int j = 0; j < 11; ++j) acc[a][j] += hreg[a] * wreg[j];
        }
    }

    #pragma unroll
    for (int a = 0; a < 8; ++a) {
        long e = ebase + g*8 + a;
        if (e < N_EDGES) {
            float cut = s_cut[g*8 + a];
            #pragma unroll
            for (int j = 0; j < 11; ++j) {
                int c = c0 + 32*j;
                g_radial[e*RCOLS + c] = (acc[a][j] + __ldg(&b2[c])) * cut;
            }
        }
    }
}

// ---------------------------------------------------------------------------
// Kernel C: tensor-product messages + float4 atomic scatter.
// One warp per edge (lane = channel u), 8 edges/block.
// ---------------------------------------------------------------------------
__global__ __launch_bounds__(256)
void msg_kernel(const float* __restrict__ nodes,
                const int*   __restrict__ src,
                const int*   __restrict__ dst,
                float*       __restrict__ out)
{
    __shared__ float s_W[NPATH * 125];
    __shared__ __align__(16) float s_row[8][288];
    __shared__ float s_M[8][120];

    const int tid = threadIdx.x, lane = tid & 31, w = tid >> 5;
    for (int i = tid; i < NPATH*125; i += 256) s_W[i] = g_W3J[i];

    const long e = (long)blockIdx.x * 8 + w;      // 250000 = 31250*8, no guard needed
    const int sn = src[e], dn = dst[e];

    // Stage source-node row (coalesced float4)
    const float4* nrow = reinterpret_cast<const float4*>(nodes + (long)sn * FEAT);
    float4* rw = reinterpret_cast<float4*>(s_row[w]);
    rw[lane]      = nrow[lane];
    rw[lane + 32] = nrow[lane + 32];
    if (lane < 8) rw[lane + 64] = nrow[lane + 64];
    __syncthreads();   // covers s_W and all rows

    // Spherical harmonics (broadcast loads)
    float yv[9];
    yv[0] = 1.0f;
    #pragma unroll
    for (int q = 0; q < 8; ++q) yv[1+q] = __ldg(&g_sph[e*8 + q]);

    // Per-lane x features (strides 3 and 5 are coprime to 32: conflict-free)
    const int u = lane;
    float xr[9];
    xr[0] = s_row[w][u];
    #pragma unroll
    for (int a = 0; a < 3; ++a) xr[1+a] = s_row[w][32 + 3*u + a];
    #pragma unroll
    for (int a = 0; a < 5; ++a) xr[4+a] = s_row[w][128 + 5*u + a];

    // Radial weights (coalesced)
    float wp[NPATH];
    #pragma unroll
    for (int p = 0; p < NPATH; ++p) wp[p] = g_radial[e*RCOLS + p*32 + u];

    // Build M_p[a][c] = sum_b W3J[p][a][b][c] * y_b cooperatively (115 entries)
    #pragma unroll
    for (int rep = 0; rep < 4; ++rep) {
        int ent = lane + rep*32;
        if (ent < MTOT) {
            int p = 0;
            #pragma unroll
            for (int q = 1; q < NPATH; ++q) if (ent >= MOFF_(q)) p = q;
            int rem = ent - MOFF_(p);
            int wk = 2*PK_(p) + 1;
            int a = rem / wk, c = rem % wk;
            int j = PJ_(p);
            const float* Wp = &s_W[p*125 + a*25 + c];
            float v;
            if (j == 0)      v = Wp[0];
            else if (j == 1) v = Wp[0]*yv[1] + Wp[5]*yv[2] + Wp[10]*yv[3];
            else             v = Wp[0]*yv[4] + Wp[5]*yv[5] + Wp[10]*yv[6]
                               + Wp[15]*yv[7] + Wp[20]*yv[8];
            s_M[w][ent] = v;
        }
    }
    __syncwarp();

    // Contraction: am[k-slot] += w_p * sum_a x[a] * M_p[a][c]  (fully unrolled)
    float am[9];
    #pragma unroll
    for (int q = 0; q < 9; ++q) am[q] = 0.0f;

    #pragma unroll
    for (int p = 0; p < NPATH; ++p) {
        const int ii = PI_(p), kk = PK_(p);
        const int wk = 2*kk + 1;
        const int mo = MOFF_(p);
        const int xb = (ii == 0) ? 0 : ((ii == 1) ? 1 : 4);
        const int ab = (kk == 0) ? 0 : ((kk == 1) ? 1 : 4);
        #pragma unroll
        for (int c = 0; c < 5; ++c) {
            if (c < wk) {
                float s = 0.0f;
                #pragma unroll
                for (int a = 0; a < 5; ++a) {
                    if (a < 2*ii + 1) s += xr[xb + a] * s_M[w][mo + a*wk + c];
                }
                am[ab + c] += wp[p] * s;
            }
        }
    }

    // Stage message row, flush as 72 coalesced float4 atomics
    __syncwarp();
    s_row[w][u] = am[0];
    #pragma unroll
    for (int c = 0; c < 3; ++c) s_row[w][32 + 3*u + c] = am[1+c];
    #pragma unroll
    for (int c = 0; c < 5; ++c) s_row[w][128 + 5*u + c] = am[4+c];
    __syncwarp();

    float4* ob = reinterpret_cast<float4*>(out) + (long)dn * (FEAT/4);
    const float4* mr = reinterpret_cast<const float4*>(s_row[w]);
    atomicAdd(&ob[lane],      mr[lane]);
    atomicAdd(&ob[lane + 32], mr[lane + 32]);
    if (lane < 8) atomicAdd(&ob[lane + 64], mr[lane + 64]);
}

// ---------------------------------------------------------------------------
// Entry point
// ---------------------------------------------------------------------------
extern "C" void kernel_launch(void* const* d_in, const int* in_sizes, int n_in,
                              void* d_out, int out_size)
{
    const float* nodes = (const float*)d_in[0];
    const float* pos   = (const float*)d_in[1];
    const int*   src   = (const int*)  d_in[2];
    const int*   dst   = (const int*)  d_in[3];
    const float* w1    = (const float*)d_in[4];
    const float* b1    = (const float*)d_in[5];
    const float* w2    = (const float*)d_in[6];
    const float* b2    = (const float*)d_in[7];
    float* out = (float*)d_out;

    w3j_init_kernel<<<NPATH, 128>>>();
    radial_kernel<<<(N_EDGES + 63) / 64, 256>>>(pos, src, dst, w1, b1, w2, b2);
    cudaMemsetAsync(out, 0, (size_t)out_size * sizeof(float));
    msg_kernel<<<N_EDGES / 8, 256>>>(nodes, src, dst, out);
}